// round 9
// baseline (speedup 1.0000x reference)
#include <cuda_runtime.h>
#include <math.h>

#define BMAX 8192
#define ONE_THIRD2 (2.0f / 3.0f)
#define FOUR_THIRDS (4.0f / 3.0f)

// Scratch (no allocations allowed)
__device__ float  g_part[4096];        // per-block partial sums of NN distance
__device__ float  g_params[2];         // [0]=1/dil, [1]=dil^2
__device__ float4 g_minv[2 * BMAX];    // per query: (i00,i01,i02,i11),(i12,i22,qx,qy)

// ---------------------------------------------------------------------------
// Cubic spline weight (matches reference piecewise formula + support mask)
// ---------------------------------------------------------------------------
__device__ __forceinline__ float cubic_w(float q) {
    float w;
    if (q <= 0.5f) w = ONE_THIRD2 + 4.f * q * q * (q - 1.f);
    else           w = FOUR_THIRDS + q * (-4.f + q * (4.f - FOUR_THIRDS * q));
    return (q <= 1.f) ? w : 0.f;
}

// ---------------------------------------------------------------------------
// Kernel 1: warp-per-node NN distance. No smem staging: nodes (32KB) are
// L1/L2 resident; __ldg float4 loads, two independent min accumulators for
// ILP. Block writes deterministic sum of its 8 distances to g_part[blockIdx].
// Each warp may cover multiple i (stride grid*8) so g_part stays <= 4096.
// ---------------------------------------------------------------------------
__global__ __launch_bounds__(256) void min_dist_kernel(const float2* __restrict__ nodes, int N) {
    __shared__ float s_d[8];
    const int tid  = threadIdx.x;
    const int lane = tid & 31;
    const int wid  = tid >> 5;
    const int N2   = N >> 1;            // pairs of nodes (N even fast path)
    const float4* n4 = (const float4*)nodes;

    float dsum = 0.f;
    for (int i = blockIdx.x * 8 + wid; i < N; i += gridDim.x * 8) {
        const float2 xi = __ldg(&nodes[i]);
        float m0 = 3.4e38f, m1 = 3.4e38f;
        for (int jj = lane; jj < N2; jj += 32) {
            const float4 v = __ldg(&n4[jj]);
            const int j0 = jj * 2;
            float dx0 = xi.x - v.x, dy0 = xi.y - v.y;
            float dx1 = xi.x - v.z, dy1 = xi.y - v.w;
            float d0 = fmaf(dx0, dx0, dy0 * dy0);
            float d1 = fmaf(dx1, dx1, dy1 * dy1);
            if (j0     != i) m0 = fminf(m0, d0);
            if (j0 + 1 != i) m1 = fminf(m1, d1);
        }
        if ((N & 1) && lane == 0 && (N - 1) != i) {
            float2 p = __ldg(&nodes[N - 1]);
            float dx = xi.x - p.x, dy = xi.y - p.y;
            m0 = fminf(m0, fmaf(dx, dx, dy * dy));
        }
        float m = fminf(m0, m1);
        #pragma unroll
        for (int o = 16; o; o >>= 1) m = fminf(m, __shfl_xor_sync(0xffffffffu, m, o));
        if (lane == 0) dsum += sqrtf(m);
    }
    if (lane == 0) s_d[wid] = dsum;
    __syncthreads();
    if (tid == 0) {
        float s = 0.f;
        #pragma unroll
        for (int w = 0; w < 8; w++) s += s_d[w];
        g_part[blockIdx.x] = s;
    }
}

// ---------------------------------------------------------------------------
// Kernel 2: moments + inversion. Warp-per-query, no smem tile (__ldg float4
// sweep over L1/L2-hot nodes). Per block: deterministic dilation reduce from
// g_part, then warp shuffle-reduces its 6-entry moment matrix; lane 0 does the
// fp64 adjugate inversion -> g_minv.
// ---------------------------------------------------------------------------
__global__ __launch_bounds__(256) void moments_kernel(const float2* __restrict__ x,
                                                      const float2* __restrict__ nodes,
                                                      int B, int N, int nblk) {
    __shared__ float s_red[256];
    const int tid = threadIdx.x;

    // deterministic dilation from per-block partials (L2-hot, fixed-order tree)
    {
        float s = 0.f;
        for (int i = tid; i < nblk; i += 256) s += g_part[i];
        s_red[tid] = s;
        __syncthreads();
        #pragma unroll
        for (int o = 128; o; o >>= 1) {
            if (tid < o) s_red[tid] += s_red[tid + o];
            __syncthreads();
        }
    }
    const float dil     = 2.5f * (s_red[0] / (float)N);
    const float inv_dil = 1.f / dil;
    const float dil2    = dil * dil;
    if (blockIdx.x == 0 && tid == 0) {
        g_params[0] = inv_dil;
        g_params[1] = dil2;
    }

    const int lane = tid & 31;
    const int qi = blockIdx.x * 8 + (tid >> 5);
    if (qi >= B) return;
    const float2 qv = __ldg(&x[qi]);
    const float4* n4 = (const float4*)nodes;
    const int N2 = N >> 1;

    float a0 = 0.f, a1 = 0.f, a2 = 0.f, a3 = 0.f, a4 = 0.f, a5 = 0.f;
    for (int jj = lane; jj < N2; jj += 32) {
        const float4 v = __ldg(&n4[jj]);
        {
            float dx = qv.x - v.x, dy = qv.y - v.y;
            float d2 = dx * dx + dy * dy + 1e-10f;
            if (d2 <= dil2) {
                float w = cubic_w(sqrtf(d2) * inv_dil);
                a0 += w;
                a1 = fmaf(w, dx, a1); a2 = fmaf(w, dy, a2);
                a3 = fmaf(w * dx, dx, a3); a4 = fmaf(w * dx, dy, a4); a5 = fmaf(w * dy, dy, a5);
            }
        }
        {
            float dx = qv.x - v.z, dy = qv.y - v.w;
            float d2 = dx * dx + dy * dy + 1e-10f;
            if (d2 <= dil2) {
                float w = cubic_w(sqrtf(d2) * inv_dil);
                a0 += w;
                a1 = fmaf(w, dx, a1); a2 = fmaf(w, dy, a2);
                a3 = fmaf(w * dx, dx, a3); a4 = fmaf(w * dx, dy, a4); a5 = fmaf(w * dy, dy, a5);
            }
        }
    }
    if ((N & 1) && lane == 0) {
        float2 p = __ldg(&nodes[N - 1]);
        float dx = qv.x - p.x, dy = qv.y - p.y;
        float d2 = dx * dx + dy * dy + 1e-10f;
        if (d2 <= dil2) {
            float w = cubic_w(sqrtf(d2) * inv_dil);
            a0 += w;
            a1 = fmaf(w, dx, a1); a2 = fmaf(w, dy, a2);
            a3 = fmaf(w * dx, dx, a3); a4 = fmaf(w * dx, dy, a4); a5 = fmaf(w * dy, dy, a5);
        }
    }
    #pragma unroll
    for (int o = 16; o; o >>= 1) {
        a0 += __shfl_xor_sync(0xffffffffu, a0, o);
        a1 += __shfl_xor_sync(0xffffffffu, a1, o);
        a2 += __shfl_xor_sync(0xffffffffu, a2, o);
        a3 += __shfl_xor_sync(0xffffffffu, a3, o);
        a4 += __shfl_xor_sync(0xffffffffu, a4, o);
        a5 += __shfl_xor_sync(0xffffffffu, a5, o);
    }
    if (lane == 0) {
        double a = (double)a0 + 1e-5, bb = (double)a1, c = (double)a2;
        double d = (double)a3 + 1e-5, e  = (double)a4, f = (double)a5 + 1e-5;
        double c00 = d * f - e * e;
        double c01 = c * e - bb * f;
        double c02 = bb * e - c * d;
        double det = a * c00 + bb * c01 + c * c02;
        double id  = 1.0 / det;
        g_minv[2 * qi]     = make_float4((float)(c00 * id), (float)(c01 * id),
                                         (float)(c02 * id), (float)((a * f - c * c) * id));
        g_minv[2 * qi + 1] = make_float4((float)((bb * c - a * e) * id),
                                         (float)((a * d - bb * bb) * id), qv.x, qv.y);
    }
}

// ---------------------------------------------------------------------------
// Kernel 3: pure streaming writer, LANE-CONTIGUOUS stores (the R7 lesson).
// Each thread: 4 consecutive n for one b. n0 = bx*1024 + tid*4, so a warp's
// float4 stores are back-to-back 16B -> full 128B lines per 8 lanes.
// No smem, no barriers; stores issue from cycle 1.
// ---------------------------------------------------------------------------
__global__ __launch_bounds__(256) void out_kernel(const float2* __restrict__ nodes,
                                                  float* __restrict__ out,
                                                  int B, int N) {
    const int b  = blockIdx.y;
    const int n0 = blockIdx.x * 1024 + threadIdx.x * 4;
    if (n0 >= N) return;

    const float4 m0 = g_minv[2 * b];
    const float4 m1 = g_minv[2 * b + 1];
    const float i00 = m0.x, i01 = m0.y, i02 = m0.z, i11 = m0.w;
    const float i12 = m1.x, i22 = m1.y, qx = m1.z, qy = m1.w;
    const float inv_dil = g_params[0];
    const float dil2    = g_params[1];

    const size_t BN = (size_t)B * (size_t)N;
    float* __restrict__ o0 = out + (size_t)b * (size_t)N;
    float* __restrict__ o1 = o0 + BN;
    float* __restrict__ o2 = o1 + BN;

    if (n0 + 3 < N) {
        const float4 nA = __ldg((const float4*)(nodes + n0));
        const float4 nB = __ldg((const float4*)(nodes + n0 + 2));
        const float ndx[4] = {nA.x, nA.z, nB.x, nB.z};
        const float ndy[4] = {nA.y, nA.w, nB.y, nB.w};
        float rp[4], rx[4], ry[4];
        #pragma unroll
        for (int j = 0; j < 4; j++) {
            float dx = qx - ndx[j];
            float dy = qy - ndy[j];
            float d2 = dx * dx + dy * dy + 1e-10f;
            if (d2 <= dil2) {
                float w = cubic_w(sqrtf(d2) * inv_dil);
                rp[j] =  w * (i00 + i01 * dx + i02 * dy);
                rx[j] = -(w * (i01 + i11 * dx + i12 * dy));
                ry[j] = -(w * (i02 + i12 * dx + i22 * dy));
            } else {
                rp[j] = 0.f; rx[j] = 0.f; ry[j] = 0.f;
            }
        }
        __stcs((float4*)(o0 + n0), make_float4(rp[0], rp[1], rp[2], rp[3]));
        __stcs((float4*)(o1 + n0), make_float4(rx[0], rx[1], rx[2], rx[3]));
        __stcs((float4*)(o2 + n0), make_float4(ry[0], ry[1], ry[2], ry[3]));
    } else {
        for (int n = n0; n < N; n++) {
            const float2 nd = __ldg(&nodes[n]);
            float dx = qx - nd.x;
            float dy = qy - nd.y;
            float d2 = dx * dx + dy * dy + 1e-10f;
            float w = (d2 <= dil2) ? cubic_w(sqrtf(d2) * inv_dil) : 0.f;
            o0[n] =  w * (i00 + i01 * dx + i02 * dy);
            o1[n] = -(w * (i01 + i11 * dx + i12 * dy));
            o2[n] = -(w * (i02 + i12 * dx + i22 * dy));
        }
    }
}

// ---------------------------------------------------------------------------
// Launch: metadata order is {x, nodes}; output is [3, B, N] fp32.
// ---------------------------------------------------------------------------
extern "C" void kernel_launch(void* const* d_in, const int* in_sizes, int n_in,
                              void* d_out, int out_size) {
    const float2* x     = (const float2*)d_in[0];
    const float2* nodes = (const float2*)d_in[1];
    float* out = (float*)d_out;
    const int B = in_sizes[0] / 2;
    const int N = in_sizes[1] / 2;

    int nblk = (N + 7) / 8;
    if (nblk > 4096) nblk = 4096;          // g_part capacity; warps stride over i
    min_dist_kernel<<<nblk, 256>>>(nodes, N);
    moments_kernel<<<(B + 7) / 8, 256>>>(x, nodes, B, N, nblk);

    dim3 grid((N + 1023) / 1024, B);
    out_kernel<<<grid, 256>>>(nodes, out, B, N);
}

// round 10
// speedup vs baseline: 1.0197x; 1.0197x over previous
#include <cuda_runtime.h>
#include <math.h>

#define BMAX 8192
#define ONE_THIRD2 (2.0f / 3.0f)
#define FOUR_THIRDS (4.0f / 3.0f)

// Scratch (no allocations allowed)
__device__ float  g_part[4096];        // per-block partial sums of NN distance
__device__ float  g_params[2];         // [0]=1/dil, [1]=dil^2
__device__ float4 g_minv[2 * BMAX];    // per query: (i00,i01,i02,i11),(i12,i22,qx,qy)

// ---------------------------------------------------------------------------
// Cubic spline weight (matches reference piecewise formula + support mask)
// ---------------------------------------------------------------------------
__device__ __forceinline__ float cubic_w(float q) {
    float w;
    if (q <= 0.5f) w = ONE_THIRD2 + 4.f * q * q * (q - 1.f);
    else           w = FOUR_THIRDS + q * (-4.f + q * (4.f - FOUR_THIRDS * q));
    return (q <= 1.f) ? w : 0.f;
}

// ---------------------------------------------------------------------------
// Kernel 1: warp-per-node NN distance. No smem staging: nodes (32KB) are
// L1/L2 resident; __ldg float4 loads, two independent min accumulators for
// ILP. Block writes deterministic sum of its 8 distances to g_part[blockIdx].
// Each warp may cover multiple i (stride grid*8) so g_part stays <= 4096.
// ---------------------------------------------------------------------------
__global__ __launch_bounds__(256) void min_dist_kernel(const float2* __restrict__ nodes, int N) {
    __shared__ float s_d[8];
    const int tid  = threadIdx.x;
    const int lane = tid & 31;
    const int wid  = tid >> 5;
    const int N2   = N >> 1;            // pairs of nodes (N even fast path)
    const float4* n4 = (const float4*)nodes;

    float dsum = 0.f;
    for (int i = blockIdx.x * 8 + wid; i < N; i += gridDim.x * 8) {
        const float2 xi = __ldg(&nodes[i]);
        float m0 = 3.4e38f, m1 = 3.4e38f;
        for (int jj = lane; jj < N2; jj += 32) {
            const float4 v = __ldg(&n4[jj]);
            const int j0 = jj * 2;
            float dx0 = xi.x - v.x, dy0 = xi.y - v.y;
            float dx1 = xi.x - v.z, dy1 = xi.y - v.w;
            float d0 = fmaf(dx0, dx0, dy0 * dy0);
            float d1 = fmaf(dx1, dx1, dy1 * dy1);
            if (j0     != i) m0 = fminf(m0, d0);
            if (j0 + 1 != i) m1 = fminf(m1, d1);
        }
        if ((N & 1) && lane == 0 && (N - 1) != i) {
            float2 p = __ldg(&nodes[N - 1]);
            float dx = xi.x - p.x, dy = xi.y - p.y;
            m0 = fminf(m0, fmaf(dx, dx, dy * dy));
        }
        float m = fminf(m0, m1);
        #pragma unroll
        for (int o = 16; o; o >>= 1) m = fminf(m, __shfl_xor_sync(0xffffffffu, m, o));
        if (lane == 0) dsum += sqrtf(m);
    }
    if (lane == 0) s_d[wid] = dsum;
    __syncthreads();
    if (tid == 0) {
        float s = 0.f;
        #pragma unroll
        for (int w = 0; w < 8; w++) s += s_d[w];
        g_part[blockIdx.x] = s;
    }
}

// ---------------------------------------------------------------------------
// Kernel 2: moments + inversion. Warp-per-query, no smem tile (__ldg float4
// sweep over L1/L2-hot nodes). Per block: deterministic dilation reduce from
// g_part, then warp shuffle-reduces its 6-entry moment matrix; lane 0 does the
// fp64 adjugate inversion -> g_minv.
// ---------------------------------------------------------------------------
__global__ __launch_bounds__(256) void moments_kernel(const float2* __restrict__ x,
                                                      const float2* __restrict__ nodes,
                                                      int B, int N, int nblk) {
    __shared__ float s_red[256];
    const int tid = threadIdx.x;

    // deterministic dilation from per-block partials (L2-hot, fixed-order tree)
    {
        float s = 0.f;
        for (int i = tid; i < nblk; i += 256) s += g_part[i];
        s_red[tid] = s;
        __syncthreads();
        #pragma unroll
        for (int o = 128; o; o >>= 1) {
            if (tid < o) s_red[tid] += s_red[tid + o];
            __syncthreads();
        }
    }
    const float dil     = 2.5f * (s_red[0] / (float)N);
    const float inv_dil = 1.f / dil;
    const float dil2    = dil * dil;
    if (blockIdx.x == 0 && tid == 0) {
        g_params[0] = inv_dil;
        g_params[1] = dil2;
    }

    const int lane = tid & 31;
    const int qi = blockIdx.x * 8 + (tid >> 5);
    if (qi >= B) return;
    const float2 qv = __ldg(&x[qi]);
    const float4* n4 = (const float4*)nodes;
    const int N2 = N >> 1;

    float a0 = 0.f, a1 = 0.f, a2 = 0.f, a3 = 0.f, a4 = 0.f, a5 = 0.f;
    for (int jj = lane; jj < N2; jj += 32) {
        const float4 v = __ldg(&n4[jj]);
        {
            float dx = qv.x - v.x, dy = qv.y - v.y;
            float d2 = dx * dx + dy * dy + 1e-10f;
            if (d2 <= dil2) {
                float w = cubic_w(sqrtf(d2) * inv_dil);
                a0 += w;
                a1 = fmaf(w, dx, a1); a2 = fmaf(w, dy, a2);
                a3 = fmaf(w * dx, dx, a3); a4 = fmaf(w * dx, dy, a4); a5 = fmaf(w * dy, dy, a5);
            }
        }
        {
            float dx = qv.x - v.z, dy = qv.y - v.w;
            float d2 = dx * dx + dy * dy + 1e-10f;
            if (d2 <= dil2) {
                float w = cubic_w(sqrtf(d2) * inv_dil);
                a0 += w;
                a1 = fmaf(w, dx, a1); a2 = fmaf(w, dy, a2);
                a3 = fmaf(w * dx, dx, a3); a4 = fmaf(w * dx, dy, a4); a5 = fmaf(w * dy, dy, a5);
            }
        }
    }
    if ((N & 1) && lane == 0) {
        float2 p = __ldg(&nodes[N - 1]);
        float dx = qv.x - p.x, dy = qv.y - p.y;
        float d2 = dx * dx + dy * dy + 1e-10f;
        if (d2 <= dil2) {
            float w = cubic_w(sqrtf(d2) * inv_dil);
            a0 += w;
            a1 = fmaf(w, dx, a1); a2 = fmaf(w, dy, a2);
            a3 = fmaf(w * dx, dx, a3); a4 = fmaf(w * dx, dy, a4); a5 = fmaf(w * dy, dy, a5);
        }
    }
    #pragma unroll
    for (int o = 16; o; o >>= 1) {
        a0 += __shfl_xor_sync(0xffffffffu, a0, o);
        a1 += __shfl_xor_sync(0xffffffffu, a1, o);
        a2 += __shfl_xor_sync(0xffffffffu, a2, o);
        a3 += __shfl_xor_sync(0xffffffffu, a3, o);
        a4 += __shfl_xor_sync(0xffffffffu, a4, o);
        a5 += __shfl_xor_sync(0xffffffffu, a5, o);
    }
    if (lane == 0) {
        double a = (double)a0 + 1e-5, bb = (double)a1, c = (double)a2;
        double d = (double)a3 + 1e-5, e  = (double)a4, f = (double)a5 + 1e-5;
        double c00 = d * f - e * e;
        double c01 = c * e - bb * f;
        double c02 = bb * e - c * d;
        double det = a * c00 + bb * c01 + c * c02;
        double id  = 1.0 / det;
        g_minv[2 * qi]     = make_float4((float)(c00 * id), (float)(c01 * id),
                                         (float)(c02 * id), (float)((a * f - c * c) * id));
        g_minv[2 * qi + 1] = make_float4((float)((bb * c - a * e) * id),
                                         (float)((a * d - bb * bb) * id), qv.x, qv.y);
    }
}

// ---------------------------------------------------------------------------
// Kernel 3: pure streaming writer, LANE-CONTIGUOUS stores (the R7 lesson).
// Each thread: 4 consecutive n for one b. n0 = bx*1024 + tid*4, so a warp's
// float4 stores are back-to-back 16B -> full 128B lines per 8 lanes.
// No smem, no barriers; stores issue from cycle 1.
// ---------------------------------------------------------------------------
__global__ __launch_bounds__(256) void out_kernel(const float2* __restrict__ nodes,
                                                  float* __restrict__ out,
                                                  int B, int N) {
    const int b  = blockIdx.y;
    const int n0 = blockIdx.x * 1024 + threadIdx.x * 4;
    if (n0 >= N) return;

    const float4 m0 = g_minv[2 * b];
    const float4 m1 = g_minv[2 * b + 1];
    const float i00 = m0.x, i01 = m0.y, i02 = m0.z, i11 = m0.w;
    const float i12 = m1.x, i22 = m1.y, qx = m1.z, qy = m1.w;
    const float inv_dil = g_params[0];
    const float dil2    = g_params[1];

    const size_t BN = (size_t)B * (size_t)N;
    float* __restrict__ o0 = out + (size_t)b * (size_t)N;
    float* __restrict__ o1 = o0 + BN;
    float* __restrict__ o2 = o1 + BN;

    if (n0 + 3 < N) {
        const float4 nA = __ldg((const float4*)(nodes + n0));
        const float4 nB = __ldg((const float4*)(nodes + n0 + 2));
        const float ndx[4] = {nA.x, nA.z, nB.x, nB.z};
        const float ndy[4] = {nA.y, nA.w, nB.y, nB.w};
        float rp[4], rx[4], ry[4];
        #pragma unroll
        for (int j = 0; j < 4; j++) {
            float dx = qx - ndx[j];
            float dy = qy - ndy[j];
            float d2 = dx * dx + dy * dy + 1e-10f;
            if (d2 <= dil2) {
                float w = cubic_w(sqrtf(d2) * inv_dil);
                rp[j] =  w * (i00 + i01 * dx + i02 * dy);
                rx[j] = -(w * (i01 + i11 * dx + i12 * dy));
                ry[j] = -(w * (i02 + i12 * dx + i22 * dy));
            } else {
                rp[j] = 0.f; rx[j] = 0.f; ry[j] = 0.f;
            }
        }
        __stcs((float4*)(o0 + n0), make_float4(rp[0], rp[1], rp[2], rp[3]));
        __stcs((float4*)(o1 + n0), make_float4(rx[0], rx[1], rx[2], rx[3]));
        __stcs((float4*)(o2 + n0), make_float4(ry[0], ry[1], ry[2], ry[3]));
    } else {
        for (int n = n0; n < N; n++) {
            const float2 nd = __ldg(&nodes[n]);
            float dx = qx - nd.x;
            float dy = qy - nd.y;
            float d2 = dx * dx + dy * dy + 1e-10f;
            float w = (d2 <= dil2) ? cubic_w(sqrtf(d2) * inv_dil) : 0.f;
            o0[n] =  w * (i00 + i01 * dx + i02 * dy);
            o1[n] = -(w * (i01 + i11 * dx + i12 * dy));
            o2[n] = -(w * (i02 + i12 * dx + i22 * dy));
        }
    }
}

// ---------------------------------------------------------------------------
// Launch: metadata order is {x, nodes}; output is [3, B, N] fp32.
// ---------------------------------------------------------------------------
extern "C" void kernel_launch(void* const* d_in, const int* in_sizes, int n_in,
                              void* d_out, int out_size) {
    const float2* x     = (const float2*)d_in[0];
    const float2* nodes = (const float2*)d_in[1];
    float* out = (float*)d_out;
    const int B = in_sizes[0] / 2;
    const int N = in_sizes[1] / 2;

    int nblk = (N + 7) / 8;
    if (nblk > 4096) nblk = 4096;          // g_part capacity; warps stride over i
    min_dist_kernel<<<nblk, 256>>>(nodes, N);
    moments_kernel<<<(B + 7) / 8, 256>>>(x, nodes, B, N, nblk);

    dim3 grid((N + 1023) / 1024, B);
    out_kernel<<<grid, 256>>>(nodes, out, B, N);
}

// round 11
// speedup vs baseline: 1.0850x; 1.0640x over previous
#include <cuda_runtime.h>
#include <math.h>

#define ONE_THIRD2  (2.0f / 3.0f)
#define FOUR_THIRDS (4.0f / 3.0f)
#define LIST_CAP    1024

// Scratch (no allocations allowed)
__device__ float g_part[4096];   // per-block partial sums of NN distance

// ---------------------------------------------------------------------------
// Cubic spline weight (matches reference piecewise formula + support mask)
// ---------------------------------------------------------------------------
__device__ __forceinline__ float cubic_w(float q) {
    float w;
    if (q <= 0.5f) w = ONE_THIRD2 + 4.f * q * q * (q - 1.f);
    else           w = FOUR_THIRDS + q * (-4.f + q * (4.f - FOUR_THIRDS * q));
    return (q <= 1.f) ? w : 0.f;
}

// ---------------------------------------------------------------------------
// Kernel 1: warp-per-node NN distance (proven). Block writes deterministic
// sum of its distances to g_part[blockIdx].
// ---------------------------------------------------------------------------
__global__ __launch_bounds__(256) void min_dist_kernel(const float2* __restrict__ nodes, int N) {
    __shared__ float s_d[8];
    const int tid  = threadIdx.x;
    const int lane = tid & 31;
    const int wid  = tid >> 5;
    const int N2   = N >> 1;
    const float4* n4 = (const float4*)nodes;

    float dsum = 0.f;
    for (int i = blockIdx.x * 8 + wid; i < N; i += gridDim.x * 8) {
        const float2 xi = __ldg(&nodes[i]);
        float m0 = 3.4e38f, m1 = 3.4e38f;
        for (int jj = lane; jj < N2; jj += 32) {
            const float4 v = __ldg(&n4[jj]);
            const int j0 = jj * 2;
            float dx0 = xi.x - v.x, dy0 = xi.y - v.y;
            float dx1 = xi.x - v.z, dy1 = xi.y - v.w;
            float d0 = fmaf(dx0, dx0, dy0 * dy0);
            float d1 = fmaf(dx1, dx1, dy1 * dy1);
            if (j0     != i) m0 = fminf(m0, d0);
            if (j0 + 1 != i) m1 = fminf(m1, d1);
        }
        if ((N & 1) && lane == 0 && (N - 1) != i) {
            float2 p = __ldg(&nodes[N - 1]);
            float dx = xi.x - p.x, dy = xi.y - p.y;
            m0 = fminf(m0, fmaf(dx, dx, dy * dy));
        }
        float m = fminf(m0, m1);
        #pragma unroll
        for (int o = 16; o; o >>= 1) m = fminf(m, __shfl_xor_sync(0xffffffffu, m, o));
        if (lane == 0) dsum += sqrtf(m);
    }
    if (lane == 0) s_d[wid] = dsum;
    __syncthreads();
    if (tid == 0) {
        float s = 0.f;
        #pragma unroll
        for (int w = 0; w < 8; w++) s += s_d[w];
        g_part[blockIdx.x] = s;
    }
}

// ---------------------------------------------------------------------------
// Kernel 2 (mega): one block per query row b.
//  A: zero-fill the row's 3 output planes with pure streaming STG.128
//     (stores flow from cycle 0 — ~99.5% of the output IS zero)
//  B: deterministic dilation reduce from g_part
//  C: one N-sweep: accumulate 6-entry moment matrix AND collect in-support
//     node indices into a smem list (order-independent)
//  D/E: fixed-order reduce + fp64 adjugate inversion (thread 0)
//  F: scatter-write only the ~21 nonzero entries per plane
// Fallback: if the list overflows (pathological data), full-row recompute.
// ---------------------------------------------------------------------------
__global__ __launch_bounds__(256) void rkpm_mega(const float2* __restrict__ x,
                                                 const float2* __restrict__ nodes,
                                                 float* __restrict__ out,
                                                 int B, int N, int nblk) {
    __shared__ float s_red[256];
    __shared__ float s_mom[8][6];
    __shared__ float s_minv[6];
    __shared__ float s_p[2];
    __shared__ int   s_list[LIST_CAP];
    __shared__ int   s_count;

    const int tid = threadIdx.x;
    const int b   = blockIdx.x;

    const size_t BN = (size_t)B * (size_t)N;
    float* __restrict__ o0 = out + (size_t)b * (size_t)N;
    float* __restrict__ o1 = o0 + BN;
    float* __restrict__ o2 = o1 + BN;

    // ---- Phase A: zero the row (3 planes), lane-contiguous streaming stores
    const float4 z4 = make_float4(0.f, 0.f, 0.f, 0.f);
    const int nv = N & ~3;
    for (int i = tid * 4; i < nv; i += 1024) {
        __stcs((float4*)(o0 + i), z4);
        __stcs((float4*)(o1 + i), z4);
        __stcs((float4*)(o2 + i), z4);
    }
    for (int i = nv + tid; i < N; i += 256) { o0[i] = 0.f; o1[i] = 0.f; o2[i] = 0.f; }

    if (tid == 0) s_count = 0;

    // ---- Phase B: deterministic dilation from per-block partials
    {
        float s = 0.f;
        for (int i = tid; i < nblk; i += 256) s += g_part[i];
        s_red[tid] = s;
        __syncthreads();
        #pragma unroll
        for (int o = 128; o; o >>= 1) {
            if (tid < o) s_red[tid] += s_red[tid + o];
            __syncthreads();
        }
        if (tid == 0) {
            float dil = 2.5f * (s_red[0] / (float)N);
            s_p[0] = 1.f / dil;
            s_p[1] = dil * dil;
        }
        __syncthreads();
    }
    const float inv_dil = s_p[0];
    const float dil2    = s_p[1];
    const float2 qv = __ldg(&x[b]);

    // ---- Phase C: moment sweep + in-support index collection
    float a0 = 0.f, a1 = 0.f, a2 = 0.f, a3 = 0.f, a4 = 0.f, a5 = 0.f;
    {
        const float4* n4 = (const float4*)nodes;
        const int N2 = N >> 1;
        for (int jj = tid; jj < N2; jj += 256) {
            const float4 v = __ldg(&n4[jj]);
            {
                float dx = qv.x - v.x, dy = qv.y - v.y;
                float d2 = dx * dx + dy * dy + 1e-10f;
                if (d2 <= dil2) {
                    float w = cubic_w(sqrtf(d2) * inv_dil);
                    a0 += w;
                    a1 = fmaf(w, dx, a1); a2 = fmaf(w, dy, a2);
                    a3 = fmaf(w * dx, dx, a3); a4 = fmaf(w * dx, dy, a4); a5 = fmaf(w * dy, dy, a5);
                    int idx = atomicAdd(&s_count, 1);
                    if (idx < LIST_CAP) s_list[idx] = 2 * jj;
                }
            }
            {
                float dx = qv.x - v.z, dy = qv.y - v.w;
                float d2 = dx * dx + dy * dy + 1e-10f;
                if (d2 <= dil2) {
                    float w = cubic_w(sqrtf(d2) * inv_dil);
                    a0 += w;
                    a1 = fmaf(w, dx, a1); a2 = fmaf(w, dy, a2);
                    a3 = fmaf(w * dx, dx, a3); a4 = fmaf(w * dx, dy, a4); a5 = fmaf(w * dy, dy, a5);
                    int idx = atomicAdd(&s_count, 1);
                    if (idx < LIST_CAP) s_list[idx] = 2 * jj + 1;
                }
            }
        }
        if ((N & 1) && tid == 0) {
            const int n = N - 1;
            float2 p = __ldg(&nodes[n]);
            float dx = qv.x - p.x, dy = qv.y - p.y;
            float d2 = dx * dx + dy * dy + 1e-10f;
            if (d2 <= dil2) {
                float w = cubic_w(sqrtf(d2) * inv_dil);
                a0 += w;
                a1 = fmaf(w, dx, a1); a2 = fmaf(w, dy, a2);
                a3 = fmaf(w * dx, dx, a3); a4 = fmaf(w * dx, dy, a4); a5 = fmaf(w * dy, dy, a5);
                int idx = atomicAdd(&s_count, 1);
                if (idx < LIST_CAP) s_list[idx] = n;
            }
        }
    }

    // ---- Phase D: fixed-order reduce (warp shuffle + 8-warp smem)
    #pragma unroll
    for (int o = 16; o; o >>= 1) {
        a0 += __shfl_xor_sync(0xffffffffu, a0, o);
        a1 += __shfl_xor_sync(0xffffffffu, a1, o);
        a2 += __shfl_xor_sync(0xffffffffu, a2, o);
        a3 += __shfl_xor_sync(0xffffffffu, a3, o);
        a4 += __shfl_xor_sync(0xffffffffu, a4, o);
        a5 += __shfl_xor_sync(0xffffffffu, a5, o);
    }
    if ((tid & 31) == 0) {
        const int w = tid >> 5;
        s_mom[w][0] = a0; s_mom[w][1] = a1; s_mom[w][2] = a2;
        s_mom[w][3] = a3; s_mom[w][4] = a4; s_mom[w][5] = a5;
    }
    __syncthreads();

    // ---- Phase E: fp64 adjugate inversion (thread 0)
    if (tid == 0) {
        float m[6];
        #pragma unroll
        for (int c = 0; c < 6; c++) {
            float s = 0.f;
            #pragma unroll
            for (int w = 0; w < 8; w++) s += s_mom[w][c];
            m[c] = s;
        }
        double a = (double)m[0] + 1e-5, bb = (double)m[1], c = (double)m[2];
        double d = (double)m[3] + 1e-5, e  = (double)m[4], f = (double)m[5] + 1e-5;
        double c00 = d * f - e * e;
        double c01 = c * e - bb * f;
        double c02 = bb * e - c * d;
        double det = a * c00 + bb * c01 + c * c02;
        double id  = 1.0 / det;
        s_minv[0] = (float)(c00 * id);
        s_minv[1] = (float)(c01 * id);
        s_minv[2] = (float)(c02 * id);
        s_minv[3] = (float)((a * f - c * c) * id);
        s_minv[4] = (float)((bb * c - a * e) * id);
        s_minv[5] = (float)((a * d - bb * bb) * id);
    }
    __syncthreads();   // also orders Phase A zeros before Phase F scatter

    const float i00 = s_minv[0], i01 = s_minv[1], i02 = s_minv[2];
    const float i11 = s_minv[3], i12 = s_minv[4], i22 = s_minv[5];
    const int cnt = s_count;

    // ---- Phase F: scatter nonzeros (or full-row fallback on overflow)
    if (cnt <= LIST_CAP) {
        for (int k = tid; k < cnt; k += 256) {
            const int n = s_list[k];
            const float2 nd = __ldg(&nodes[n]);
            float dx = qv.x - nd.x;
            float dy = qv.y - nd.y;
            float d2 = dx * dx + dy * dy + 1e-10f;
            float w = cubic_w(sqrtf(d2) * inv_dil);
            o0[n] =  w * (i00 + i01 * dx + i02 * dy);
            o1[n] = -(w * (i01 + i11 * dx + i12 * dy));
            o2[n] = -(w * (i02 + i12 * dx + i22 * dy));
        }
    } else {
        for (int n = tid; n < N; n += 256) {
            const float2 nd = __ldg(&nodes[n]);
            float dx = qv.x - nd.x;
            float dy = qv.y - nd.y;
            float d2 = dx * dx + dy * dy + 1e-10f;
            if (d2 <= dil2) {
                float w = cubic_w(sqrtf(d2) * inv_dil);
                o0[n] =  w * (i00 + i01 * dx + i02 * dy);
                o1[n] = -(w * (i01 + i11 * dx + i12 * dy));
                o2[n] = -(w * (i02 + i12 * dx + i22 * dy));
            }
        }
    }
}

// ---------------------------------------------------------------------------
// Launch: metadata order is {x, nodes}; output is [3, B, N] fp32.
// ---------------------------------------------------------------------------
extern "C" void kernel_launch(void* const* d_in, const int* in_sizes, int n_in,
                              void* d_out, int out_size) {
    const float2* x     = (const float2*)d_in[0];
    const float2* nodes = (const float2*)d_in[1];
    float* out = (float*)d_out;
    const int B = in_sizes[0] / 2;
    const int N = in_sizes[1] / 2;

    int nblk = (N + 7) / 8;
    if (nblk > 4096) nblk = 4096;
    min_dist_kernel<<<nblk, 256>>>(nodes, N);
    rkpm_mega<<<B, 256>>>(x, nodes, out, B, N, nblk);
}